// round 15
// baseline (speedup 1.0000x reference)
#include <cuda_runtime.h>

// ----------------------------------------------------------------------------
// complex_feature_renet — GB300 sm_103a, round 11
// R8 design with corrected slack: [H][C][L][B] layout, per-ho zero-padded
// weights (guard-free mainloop), dup-B smem (no packs), TM=8, forced occupancy.
// SLK sized to worst out-of-range B read (conv2: 3.78M floats) with margin.
// ----------------------------------------------------------------------------

#define BFIX 1024
#define SLK (4 * 1024 * 1024)

// activations with leading/trailing slack (slack stays zero -> 0*w = 0, no NaN)
__device__ float g_xT [2 * SLK + 5 * 127 * BFIX];
__device__ float g_t0 [2 * SLK + 5 * 5   * 127 * BFIX];
__device__ float g_t1 [2 * SLK + 5 * 5   * 81  * BFIX];
__device__ float g_t2 [2 * SLK + 5 * 25  * 81  * BFIX];
__device__ float g_t3 [2 * SLK + 5 * 1   * 81  * BFIX];
__device__ float g_t5 [2 * SLK + 5 * 75  * 81  * BFIX];
__device__ float g_t6 [2 * SLK + 5 * 75  * 41  * BFIX];
__device__ float g_t7 [2 * SLK + 5 * 150 * 41  * BFIX];
__device__ float g_t8 [2 * SLK + 5 * 25  * 41  * BFIX];
__device__ float g_t9 [2 * SLK + 4 * 300 * 41  * BFIX];
__device__ float g_t10[2 * SLK + 4 * 300 * 18  * BFIX];
__device__ float g_t12[2 * SLK + 5 * 150 * 18  * BFIX];
__device__ float g_t13[2 * SLK + 3 * 512 * 18  * BFIX];

// per-ho zero-padded conv weights [nho][Mpad][Kpad]
__device__ float g_wp0b[5 * 32 * 16];
__device__ float g_wp0c[5 * 32 * 16];
__device__ float g_wp1 [5 * 80 * 80];
__device__ float g_wpa [5 * 160 * 32];
__device__ float g_wp2 [5 * 160 * 240];
__device__ float g_wp3 [4 * 320 * 304];
__device__ float g_wp4 [3 * 512 * 608];
__device__ float g_wpb [3 * 512 * 464];
// zero-padded linear weights [Mpad][Kpad]
__device__ float g_pl0[96 * 128];
__device__ float g_pr0[96 * 128];
__device__ float g_pl1[48 * 96];
__device__ float g_pra[48 * 96];
__device__ float g_pl2[24 * 48];
__device__ float g_prb[24 * 48];

// ---------------- f32x2 helpers ----------------
__device__ __forceinline__ void fma2(unsigned long long& c, unsigned long long a,
                                     unsigned long long b) {
    asm("fma.rn.f32x2 %0, %1, %2, %0;" : "+l"(c) : "l"(a), "l"(b));
}
__device__ __forceinline__ float2 unpack2(unsigned long long v) {
    float2 r;
    asm("mov.b64 {%0, %1}, %2;" : "=f"(r.x), "=f"(r.y) : "l"(v));
    return r;
}

// ---------------- weight prep: pad + per-ho fold ----------------
struct Job {
    const float* src;
    float* dst;
    int O, C, KH, pad, H_in, Mpad, Kpad, nho;  // KH==0 -> linear (C = K)
};
struct JobTab { Job j[14]; };

__global__ void prep_kernel(JobTab jt) {
    Job job = jt.j[blockIdx.y];
    int tot = job.nho * job.Mpad * job.Kpad;
    int MK = job.Mpad * job.Kpad;
    for (int idx = blockIdx.x * 256 + threadIdx.x; idx < tot;
         idx += gridDim.x * 256) {
        int ho = idx / MK;
        int r = idx - ho * MK;
        int m = r / job.Kpad, k = r - m * job.Kpad;
        float v = 0.f;
        if (job.KH == 0) {
            if (m < job.O && k < job.C) v = job.src[m * job.C + k];
        } else {
            if (m < job.O && k < job.KH * job.C) {
                int kh = k / job.C, i = k - kh * job.C;
                int h = ho - job.pad + kh;
                if (h >= 0 && h < job.H_in)
                    v = job.src[(m * job.C + i) * job.KH + kh];
            }
        }
        job.dst[idx] = v;
    }
}

// ---------------- x transpose ----------------
__global__ void xpose_kernel(const float* __restrict__ x, float* __restrict__ xT,
                             int B) {
    __shared__ float sm[32][33];
    int h = blockIdx.z;
    int l0 = blockIdx.x * 32, b0 = blockIdx.y * 32;
    int tx = threadIdx.x, ty = threadIdx.y;
#pragma unroll
    for (int j = 0; j < 4; j++) {
        int b = b0 + ty + j * 8, l = l0 + tx;
        if (l < 127) sm[ty + j * 8][tx] = x[((size_t)b * 5 + h) * 127 + l];
    }
    __syncthreads();
#pragma unroll
    for (int j = 0; j < 4; j++) {
        int l = l0 + ty + j * 8, b = b0 + tx;
        if (l < 127) xT[((size_t)h * 127 + l) * B + b] = sm[tx][ty + j * 8];
    }
}

// ---------------- conv0a ----------------
__global__ void conv0a_kernel(const float* __restrict__ xT, const float* __restrict__ w,
                              const float* __restrict__ bias, float* __restrict__ out,
                              int B) {
    int n = blockIdx.x * blockDim.x + threadIdx.x;
    int N = 127 * B;
    if (n >= N) return;
    float xv[5];
#pragma unroll
    for (int h = 0; h < 5; h++) xv[h] = xT[(size_t)h * N + n];
    float wv[5][3];
#pragma unroll
    for (int c = 0; c < 5; c++)
#pragma unroll
        for (int dh = 0; dh < 3; dh++) wv[c][dh] = w[c * 3 + dh];
#pragma unroll
    for (int ho = 0; ho < 5; ho++) {
#pragma unroll
        for (int c = 0; c < 5; c++) {
            float acc = bias[c];
#pragma unroll
            for (int dh = 0; dh < 3; dh++) {
                int hi = ho + dh - 1;
                if (hi >= 0 && hi < 5) acc = fmaf(wv[c][dh], xv[hi], acc);
            }
            out[(size_t)(ho * 5 + c) * N + n] = acc;
        }
    }
}

// ---------------- unified GEMM: guard-free mainloop, dup-B smem ----------------
// flags: bit0 = accumulate, bit1 = relu
template <int BM, int BN, bool LINM, int MINB>
__global__ __launch_bounds__((BM / 8) * (BN / 8), MINB)
void gemm_kernel(const float* __restrict__ A, int Kpad,
                 const float* __restrict__ bias,
                 const float* __restrict__ Bb, float* __restrict__ Cb,
                 int groupK, int C_out, int pad, int ldB, int flags) {
    constexpr int NT = (BM / 8) * (BN / 8), BK = 16, ASR = BM + 4;
    constexpr int TOTF4 = BK * BN / 4;
    constexpr int F4 = (TOTF4 + NT - 1) / NT;
    constexpr int CPT = BK * BM / NT;        // A floats per thread per tile
    constexpr int TPR = BK / CPT;            // threads per A row
    constexpr int AV = CPT / 4;              // A float4s per thread

    __shared__ __align__(16) float As[BK * ASR];
    __shared__ __align__(16) float Bs[BK * 2 * BN];

    const int t = threadIdx.x;
    const int bm0 = blockIdx.y * BM;

    const float* Ap;
    const float* Bp;
    float* Cp;
    if (LINM) {
        int nb = ldB / BN;
        int g = blockIdx.x / nb;
        int nbi = blockIdx.x - g * nb;
        Ap = A;
        Bp = Bb + (size_t)g * groupK * ldB + nbi * BN;
        Cp = Cb + (size_t)g * C_out * ldB + nbi * BN;
    } else {
        int ho = blockIdx.z;
        int hs = ho - pad;
        int Mpad = gridDim.y * BM;
        Ap = A + (size_t)ho * Mpad * Kpad;
        Bp = Bb + (ptrdiff_t)hs * groupK * ldB + (size_t)blockIdx.x * BN;
        Cp = Cb + (size_t)ho * C_out * ldB + (size_t)blockIdx.x * BN;
    }

    const int am = t / TPR;
    const int ak0 = (t % TPR) * CPT;
    const int gm = bm0 + am;
    const int tidn = t % (BN / 8), tidm = t / (BN / 8);
    const int tm0 = tidm * 8, tn0 = tidn * 8;

    unsigned long long acc[4][8];
#pragma unroll
    for (int i = 0; i < 4; i++)
#pragma unroll
        for (int j = 0; j < 8; j++) acc[i][j] = 0ull;

    const int nk = Kpad / BK;
    const float* Arow = Ap + (size_t)gm * Kpad + ak0;

    // tile 0 -> smem
#pragma unroll
    for (int v = 0; v < AV; v++) {
        float4 a4 = *reinterpret_cast<const float4*>(Arow + 4 * v);
        As[(ak0 + 4 * v + 0) * ASR + am] = a4.x;
        As[(ak0 + 4 * v + 1) * ASR + am] = a4.y;
        As[(ak0 + 4 * v + 2) * ASR + am] = a4.z;
        As[(ak0 + 4 * v + 3) * ASR + am] = a4.w;
    }
#pragma unroll
    for (int i = 0; i < F4; i++) {
        int e = t + i * NT;
        if (e < TOTF4) {
            int k = e / (BN / 4), c4 = (e - k * (BN / 4)) * 4;
            float4 v = *reinterpret_cast<const float4*>(Bp + (size_t)k * ldB + c4);
            *reinterpret_cast<float4*>(&Bs[k * 2 * BN + 2 * c4]) =
                make_float4(v.x, v.x, v.y, v.y);
            *reinterpret_cast<float4*>(&Bs[k * 2 * BN + 2 * c4 + 4]) =
                make_float4(v.z, v.z, v.w, v.w);
        }
    }
    __syncthreads();

    for (int kt = 0; kt < nk; kt++) {
        float4 arg[AV];
        float4 brg[F4];
        const bool has = (kt + 1 < nk);
        if (has) {
            int kb = (kt + 1) * BK;
#pragma unroll
            for (int v = 0; v < AV; v++)
                arg[v] = *reinterpret_cast<const float4*>(Arow + kb + 4 * v);
#pragma unroll
            for (int i = 0; i < F4; i++) {
                int e = t + i * NT;
                if (e < TOTF4) {
                    int k = e / (BN / 4), c4 = (e - k * (BN / 4)) * 4;
                    brg[i] = *reinterpret_cast<const float4*>(
                        Bp + (size_t)(kb + k) * ldB + c4);
                }
            }
        }
#pragma unroll
        for (int k = 0; k < BK; k++) {
            ulonglong2 a01 = *reinterpret_cast<const ulonglong2*>(&As[k * ASR + tm0]);
            ulonglong2 a23 = *reinterpret_cast<const ulonglong2*>(&As[k * ASR + tm0 + 4]);
            unsigned long long au[4] = {a01.x, a01.y, a23.x, a23.y};
            const float* br = &Bs[k * 2 * BN + 2 * tn0];
            ulonglong2 b0 = *reinterpret_cast<const ulonglong2*>(br);
            ulonglong2 b1 = *reinterpret_cast<const ulonglong2*>(br + 4);
            ulonglong2 b2 = *reinterpret_cast<const ulonglong2*>(br + 8);
            ulonglong2 b3 = *reinterpret_cast<const ulonglong2*>(br + 12);
            unsigned long long bd[8] = {b0.x, b0.y, b1.x, b1.y,
                                        b2.x, b2.y, b3.x, b3.y};
#pragma unroll
            for (int i = 0; i < 4; i++)
#pragma unroll
                for (int j = 0; j < 8; j++) fma2(acc[i][j], au[i], bd[j]);
        }
        __syncthreads();
        if (has) {
#pragma unroll
            for (int v = 0; v < AV; v++) {
                As[(ak0 + 4 * v + 0) * ASR + am] = arg[v].x;
                As[(ak0 + 4 * v + 1) * ASR + am] = arg[v].y;
                As[(ak0 + 4 * v + 2) * ASR + am] = arg[v].z;
                As[(ak0 + 4 * v + 3) * ASR + am] = arg[v].w;
            }
#pragma unroll
            for (int i = 0; i < F4; i++) {
                int e = t + i * NT;
                if (e < TOTF4) {
                    int k = e / (BN / 4), c4 = (e - k * (BN / 4)) * 4;
                    float4 v = brg[i];
                    *reinterpret_cast<float4*>(&Bs[k * 2 * BN + 2 * c4]) =
                        make_float4(v.x, v.x, v.y, v.y);
                    *reinterpret_cast<float4*>(&Bs[k * 2 * BN + 2 * c4 + 4]) =
                        make_float4(v.z, v.z, v.w, v.w);
                }
            }
            __syncthreads();
        }
    }

    const bool accf = (flags & 1);
    const bool relu = (flags & 2);
#pragma unroll
    for (int i = 0; i < 4; i++) {
        float2 pr[8];
#pragma unroll
        for (int j = 0; j < 8; j++) pr[j] = unpack2(acc[i][j]);
#pragma unroll
        for (int r = 0; r < 2; r++) {
            int m = bm0 + tm0 + 2 * i + r;
            if (m >= C_out) continue;
            float bs = bias[m];
            float* cp = Cp + (size_t)m * ldB + tn0;
            float4 v0, v1;
            if (r == 0) {
                v0 = make_float4(pr[0].x + bs, pr[1].x + bs, pr[2].x + bs, pr[3].x + bs);
                v1 = make_float4(pr[4].x + bs, pr[5].x + bs, pr[6].x + bs, pr[7].x + bs);
            } else {
                v0 = make_float4(pr[0].y + bs, pr[1].y + bs, pr[2].y + bs, pr[3].y + bs);
                v1 = make_float4(pr[4].y + bs, pr[5].y + bs, pr[6].y + bs, pr[7].y + bs);
            }
            if (accf) {
                float4 q0 = *reinterpret_cast<const float4*>(cp);
                float4 q1 = *reinterpret_cast<const float4*>(cp + 4);
                v0.x += q0.x; v0.y += q0.y; v0.z += q0.z; v0.w += q0.w;
                v1.x += q1.x; v1.y += q1.y; v1.z += q1.z; v1.w += q1.w;
            }
            if (relu) {
                v0.x = fmaxf(v0.x, 0.f); v0.y = fmaxf(v0.y, 0.f);
                v0.z = fmaxf(v0.z, 0.f); v0.w = fmaxf(v0.w, 0.f);
                v1.x = fmaxf(v1.x, 0.f); v1.y = fmaxf(v1.y, 0.f);
                v1.z = fmaxf(v1.z, 0.f); v1.w = fmaxf(v1.w, 0.f);
            }
            *reinterpret_cast<float4*>(cp) = v0;
            *reinterpret_cast<float4*>(cp + 4) = v1;
        }
    }
}

// ---------------- final transpose ----------------
__global__ __launch_bounds__(256) void ftrans_kernel(const float* __restrict__ t13,
                                                     float* __restrict__ out, int B) {
    __shared__ float sm[128 * 19];
    int b0 = blockIdx.x * 128;
    int m = blockIdx.y, ho = blockIdx.z;
    int t = threadIdx.x;
    for (int idx = t; idx < 18 * 128; idx += 256) {
        int l = idx >> 7, b = idx & 127;
        sm[b * 19 + l] = t13[((size_t)(ho * 512 + m) * 18 + l) * B + b0 + b];
    }
    __syncthreads();
    for (int idx = t; idx < 128 * 18; idx += 256) {
        int b = idx / 18, l = idx - 18 * b;
        out[((size_t)(b0 + b) * 512 + m) * 54 + ho * 18 + l] = sm[b * 19 + l];
    }
}

// ---------------- host launcher ----------------
extern "C" void kernel_launch(void* const* d_in, const int* in_sizes, int n_in,
                              void* d_out, int out_size) {
    const float* x   = (const float*)d_in[0];
    const float* W0a = (const float*)d_in[1];
    const float* b0a = (const float*)d_in[2];
    const float* Wl0 = (const float*)d_in[3];
    const float* bl0 = (const float*)d_in[4];
    const float* W0b = (const float*)d_in[5];
    const float* b0b = (const float*)d_in[6];
    const float* Wr0 = (const float*)d_in[7];
    const float* br0 = (const float*)d_in[8];
    const float* W0c = (const float*)d_in[9];
    const float* b0c = (const float*)d_in[10];
    const float* W1  = (const float*)d_in[11];
    const float* b1  = (const float*)d_in[12];
    const float* Wl1 = (const float*)d_in[13];
    const float* bl1 = (const float*)d_in[14];
    const float* W2  = (const float*)d_in[15];
    const float* b2  = (const float*)d_in[16];
    const float* Wra = (const float*)d_in[17];
    const float* bra = (const float*)d_in[18];
    const float* Wa  = (const float*)d_in[19];
    const float* ba  = (const float*)d_in[20];
    const float* W3  = (const float*)d_in[21];
    const float* b3  = (const float*)d_in[22];
    const float* Wl2 = (const float*)d_in[23];
    const float* bl2 = (const float*)d_in[24];
    const float* W4  = (const float*)d_in[25];
    const float* b4  = (const float*)d_in[26];
    const float* Wrb = (const float*)d_in[27];
    const float* brb = (const float*)d_in[28];
    const float* Wb  = (const float*)d_in[29];
    const float* bb  = (const float*)d_in[30];

    const int B = in_sizes[0] / (5 * 127);
    const int N81 = 81 * B, N41 = 41 * B, N18 = 18 * B;

    auto gsym = [](void* s) {
        void* p;
        cudaGetSymbolAddress(&p, (const void*)s);
        return (float*)p;
    };
    float* xT  = gsym((void*)g_xT)  + SLK;
    float* t0  = gsym((void*)g_t0)  + SLK;
    float* t1  = gsym((void*)g_t1)  + SLK;
    float* t2  = gsym((void*)g_t2)  + SLK;
    float* t3  = gsym((void*)g_t3)  + SLK;
    float* t5  = gsym((void*)g_t5)  + SLK;
    float* t6  = gsym((void*)g_t6)  + SLK;
    float* t7  = gsym((void*)g_t7)  + SLK;
    float* t8  = gsym((void*)g_t8)  + SLK;
    float* t9  = gsym((void*)g_t9)  + SLK;
    float* t10 = gsym((void*)g_t10) + SLK;
    float* t12 = gsym((void*)g_t12) + SLK;
    float* t13 = gsym((void*)g_t13) + SLK;
    float* wp0b = gsym((void*)g_wp0b);
    float* wp0c = gsym((void*)g_wp0c);
    float* wp1  = gsym((void*)g_wp1);
    float* wpa  = gsym((void*)g_wpa);
    float* wp2  = gsym((void*)g_wp2);
    float* wp3  = gsym((void*)g_wp3);
    float* wp4  = gsym((void*)g_wp4);
    float* wpb  = gsym((void*)g_wpb);
    float* pl0  = gsym((void*)g_pl0);
    float* pr0  = gsym((void*)g_pr0);
    float* pl1  = gsym((void*)g_pl1);
    float* pra  = gsym((void*)g_pra);
    float* pl2  = gsym((void*)g_pl2);
    float* prb  = gsym((void*)g_prb);

    JobTab jt;
    jt.j[0]  = {W0b, wp0b, 25, 5, 3, 1, 5, 32, 16, 5};
    jt.j[1]  = {W0c, wp0c, 25, 1, 1, 0, 5, 32, 16, 5};
    jt.j[2]  = {W1, wp1, 75, 25, 3, 1, 5, 80, 80, 5};
    jt.j[3]  = {Wa, wpa, 150, 25, 1, 0, 5, 160, 32, 5};
    jt.j[4]  = {W2, wp2, 150, 75, 3, 1, 5, 160, 240, 5};
    jt.j[5]  = {W3, wp3, 300, 150, 2, 0, 5, 320, 304, 4};
    jt.j[6]  = {W4, wp4, 512, 300, 2, 0, 4, 512, 608, 3};
    jt.j[7]  = {Wb, wpb, 512, 150, 3, 0, 5, 512, 464, 3};
    jt.j[8]  = {Wl0, pl0, 81, 127, 0, 0, 0, 96, 128, 1};
    jt.j[9]  = {Wr0, pr0, 81, 127, 0, 0, 0, 96, 128, 1};
    jt.j[10] = {Wl1, pl1, 41, 81, 0, 0, 0, 48, 96, 1};
    jt.j[11] = {Wra, pra, 41, 81, 0, 0, 0, 48, 96, 1};
    jt.j[12] = {Wl2, pl2, 18, 41, 0, 0, 0, 24, 48, 1};
    jt.j[13] = {Wrb, prb, 18, 41, 0, 0, 0, 24, 48, 1};
    prep_kernel<<<dim3(512, 14), 256>>>(jt);

    xpose_kernel<<<dim3(4, B / 32, 5), dim3(32, 8)>>>(x, xT, B);

    // ---- block 0 ----
    conv0a_kernel<<<(127 * B + 255) / 256, 256>>>(xT, W0a, b0a, t0, B);
    gemm_kernel<48, 64, true, 10><<<dim3(25 * (B / 64), 2), 48>>>(
        pl0, 128, bl0, t0, t1, 127, 81, 0, B, 2);
    gemm_kernel<32, 128, false, 6><<<dim3(N81 / 128, 1, 5), 64>>>(
        wp0b, 16, b0b, t1, t2, 5, 25, 1, N81, 0);
    gemm_kernel<48, 64, true, 10><<<dim3(5 * (B / 64), 2), 48>>>(
        pr0, 128, br0, xT, t3, 127, 81, 0, B, 0);
    gemm_kernel<32, 128, false, 6><<<dim3(N81 / 128, 1, 5), 64>>>(
        wp0c, 16, b0c, t3, t2, 1, 25, 0, N81, 1);
    // t2 = x1

    // ---- block 1 ----
    gemm_kernel<80, 128, false, 3><<<dim3(N81 / 128, 1, 5), 160>>>(
        wp1, 80, b1, t2, t5, 25, 75, 1, N81, 0);
    gemm_kernel<48, 128, true, 5><<<dim3(375 * (B / 128), 1), 96>>>(
        pl1, 96, bl1, t5, t6, 81, 41, 0, B, 2);
    gemm_kernel<80, 128, false, 3><<<dim3(N41 / 128, 2, 5), 160>>>(
        wp2, 240, b2, t6, t7, 75, 150, 1, N41, 0);
    gemm_kernel<48, 128, true, 5><<<dim3(125 * (B / 128), 1), 96>>>(
        pra, 96, bra, t2, t8, 81, 41, 0, B, 0);
    gemm_kernel<80, 128, false, 3><<<dim3(N41 / 128, 2, 5), 160>>>(
        wpa, 32, ba, t8, t7, 25, 150, 0, N41, 1);
    // t7 = x2

    // ---- block 2 ----
    gemm_kernel<80, 128, false, 3><<<dim3(N41 / 128, 4, 4), 160>>>(
        wp3, 304, b3, t7, t9, 150, 300, 0, N41, 0);
    gemm_kernel<24, 128, true, 8><<<dim3(1200 * (B / 128), 1), 48>>>(
        pl2, 48, bl2, t9, t10, 41, 18, 0, B, 2);
    gemm_kernel<128, 128, false, 2><<<dim3(N18 / 128, 4, 3), 256>>>(
        wp4, 608, b4, t10, t13, 300, 512, 0, N18, 0);
    gemm_kernel<24, 128, true, 8><<<dim3(750 * (B / 128), 1), 48>>>(
        prb, 48, brb, t7, t12, 41, 18, 0, B, 0);
    gemm_kernel<128, 128, false, 2><<<dim3(N18 / 128, 4, 3), 256>>>(
        wpb, 464, bb, t12, t13, 150, 512, 0, N18, 1);
    ftrans_kernel<<<dim3(B / 128, 512, 3), 256>>>(t13, (float*)d_out, B);
}

// round 16
// speedup vs baseline: 1.5749x; 1.5749x over previous
#include <cuda_runtime.h>

// ----------------------------------------------------------------------------
// complex_feature_renet — GB300 sm_103a, round 15
// Restored round-3 design (best: 3249us) exactly; only change: BK is a
// template param, BK=32 for the two largest GEMMs (conv4, convb) to halve
// barrier/tile-refill rounds there. Everything else bit-identical.
// ----------------------------------------------------------------------------

#define BFIX 1024

__device__ float g_xT [5 * 127 * BFIX];
__device__ float g_t0 [5 * 5   * 127 * BFIX];
__device__ float g_t1 [5 * 5   * 81  * BFIX];
__device__ float g_t2 [5 * 25  * 81  * BFIX];
__device__ float g_t3 [5 * 1   * 81  * BFIX];
__device__ float g_t5 [5 * 75  * 81  * BFIX];
__device__ float g_t6 [5 * 75  * 41  * BFIX];
__device__ float g_t7 [5 * 150 * 41  * BFIX];
__device__ float g_t8 [5 * 25  * 41  * BFIX];
__device__ float g_t9 [4 * 300 * 41  * BFIX];
__device__ float g_t10[4 * 300 * 18  * BFIX];
__device__ float g_t12[5 * 150 * 18  * BFIX];
__device__ float g_t13[3 * 512 * 18  * BFIX];

__device__ float g_wp0b[25  * 15 ];
__device__ float g_wp1 [75  * 75 ];
__device__ float g_wp2 [150 * 225];
__device__ float g_wp3 [300 * 300];
__device__ float g_wp4 [512 * 600];
__device__ float g_wpb [512 * 450];

// ---------------- f32x2 helpers ----------------
__device__ __forceinline__ unsigned long long pack2(float x, float y) {
    unsigned long long r;
    asm("mov.b64 %0, {%1, %2};" : "=l"(r) : "f"(x), "f"(y));
    return r;
}
__device__ __forceinline__ void fma2(unsigned long long& c, unsigned long long a,
                                     unsigned long long b) {
    asm("fma.rn.f32x2 %0, %1, %2, %0;" : "+l"(c) : "l"(a), "l"(b));
}
__device__ __forceinline__ float2 unpack2(unsigned long long v) {
    float2 r;
    asm("mov.b64 {%0, %1}, %2;" : "=f"(r.x), "=f"(r.y) : "l"(v));
    return r;
}

// ---------------- fused weight fold ----------------
struct P6 {
    const float *s0, *s1, *s2, *s3, *s4, *s5;
    float *d0, *d1, *d2, *d3, *d4, *d5;
};
__global__ void permute_all_kernel(P6 p) {
    int idx = blockIdx.x * blockDim.x + threadIdx.x;
    const float* s; float* d; int C, KH, base;
    if (idx < 375)        { s = p.s0; d = p.d0; C = 5;   KH = 3; base = 0; }
    else if (idx < 6000)  { s = p.s1; d = p.d1; C = 25;  KH = 3; base = 375; }
    else if (idx < 39750) { s = p.s2; d = p.d2; C = 75;  KH = 3; base = 6000; }
    else if (idx < 129750){ s = p.s3; d = p.d3; C = 150; KH = 2; base = 39750; }
    else if (idx < 436950){ s = p.s4; d = p.d4; C = 300; KH = 2; base = 129750; }
    else if (idx < 667350){ s = p.s5; d = p.d5; C = 150; KH = 3; base = 436950; }
    else return;
    int local = idx - base;
    int o = local / (KH * C);
    int rem = local - o * (KH * C);
    int dh = rem / C;
    int i = rem - dh * C;
    d[local] = s[(o * C + i) * KH + dh];
}

// ---------------- x transpose ----------------
__global__ void xpose_kernel(const float* __restrict__ x, float* __restrict__ xT,
                             int B) {
    __shared__ float sm[32][33];
    int h = blockIdx.z;
    int l0 = blockIdx.x * 32, b0 = blockIdx.y * 32;
    int tx = threadIdx.x, ty = threadIdx.y;
#pragma unroll
    for (int j = 0; j < 4; j++) {
        int b = b0 + ty + j * 8, l = l0 + tx;
        if (l < 127) sm[ty + j * 8][tx] = x[((size_t)b * 5 + h) * 127 + l];
    }
    __syncthreads();
#pragma unroll
    for (int j = 0; j < 4; j++) {
        int l = l0 + ty + j * 8, b = b0 + tx;
        if (l < 127) xT[((size_t)h * 127 + l) * B + b] = sm[tx][ty + j * 8];
    }
}

// ---------------- conv0a ----------------
__global__ void conv0a_kernel(const float* __restrict__ xT, const float* __restrict__ w,
                              const float* __restrict__ bias, float* __restrict__ out,
                              int B) {
    int n = blockIdx.x * blockDim.x + threadIdx.x;
    int N = 127 * B;
    if (n >= N) return;
    float xv[5];
#pragma unroll
    for (int h = 0; h < 5; h++) xv[h] = xT[(size_t)h * N + n];
    float wv[5][3];
#pragma unroll
    for (int c = 0; c < 5; c++)
#pragma unroll
        for (int dh = 0; dh < 3; dh++) wv[c][dh] = w[c * 3 + dh];
#pragma unroll
    for (int ho = 0; ho < 5; ho++) {
#pragma unroll
        for (int c = 0; c < 5; c++) {
            float acc = bias[c];
#pragma unroll
            for (int dh = 0; dh < 3; dh++) {
                int hi = ho + dh - 1;
                if (hi >= 0 && hi < 5) acc = fmaf(wv[c][dh], xv[hi], acc);
            }
            out[(size_t)(ho * 5 + c) * N + n] = acc;
        }
    }
}

// ---------------- unified GEMM (round-3 proven design, BK templated) --------
// flags: bit0 = accumulate, bit1 = relu
template <int BM, bool LINM, int BK = 16>
__global__ __launch_bounds__(BM * 2, (BM == 128 ? 2 : BM == 64 ? 4 : BM == 48 ? 4 : 6))
void gemm_kernel(const float* __restrict__ A, int lda,
                 const float* __restrict__ bias,
                 const float* __restrict__ Bb, float* __restrict__ Cb,
                 int C_in, int C_out, int KH, int pad, int H_in,
                 int ldB, int flags) {
    constexpr int NT = BM * 2, BN = 128, ASR = BM + 4;
    constexpr int CPT = BK / 2;                 // A elems per thread per tile
    constexpr int TOT4 = BK * BN / 4;           // B float4s per tile
    constexpr int F4 = (TOT4 + NT - 1) / NT;    // B float4 loads per thread
    __shared__ __align__(16) float As[BK * ASR];
    __shared__ __align__(16) float Bs[BK * BN];

    const int t = threadIdx.x;
    const int bm0 = blockIdx.y * BM;

    int K;
    const float* Ap;
    const float* Bp;
    float* Cp;
    if (LINM) {
        K = C_in;
        int nb = ldB >> 7;
        int g = blockIdx.x / nb;
        int nbi = blockIdx.x - g * nb;
        Ap = A;
        Bp = Bb + (size_t)g * K * ldB + nbi * BN;
        Cp = Cb + (size_t)g * C_out * ldB + nbi * BN;
    } else {
        int ho = blockIdx.z;
        int hs = ho - pad;
        int h0 = hs > 0 ? hs : 0;
        int he = hs + KH; if (he > H_in) he = H_in;
        K = (he - h0) * C_in;
        Ap = A + (h0 - hs) * C_in;
        Bp = Bb + (size_t)h0 * C_in * ldB + (size_t)blockIdx.x * BN;
        Cp = Cb + (size_t)ho * C_out * ldB + (size_t)blockIdx.x * BN;
    }

    const int am = t >> 1;
    const int ak0 = (t & 1) * CPT;
    const int gm = bm0 + am;
    const int tidm = t / 16, tidn = t % 16;
    const int tm0 = tidm * 8, tn0 = tidn * 8;

    unsigned long long acc[8][4];
#pragma unroll
    for (int i = 0; i < 8; i++)
#pragma unroll
        for (int j = 0; j < 4; j++) acc[i][j] = 0ull;

    const int nk = (K + BK - 1) / BK;

    // tile 0 -> smem
#pragma unroll
    for (int j = 0; j < CPT; j++) {
        int gk = ak0 + j;
        float v = (gm < C_out && gk < K) ? Ap[(size_t)gm * lda + gk] : 0.f;
        As[gk * ASR + am] = v;
    }
#pragma unroll
    for (int i = 0; i < F4; i++) {
        int e = t + i * NT;
        if (e < TOT4) {
            int k = e >> 5, c4 = (e & 31) * 4;
            float4 v = make_float4(0.f, 0.f, 0.f, 0.f);
            if (k < K) v = *reinterpret_cast<const float4*>(Bp + (size_t)k * ldB + c4);
            *reinterpret_cast<float4*>(&Bs[k * BN + c4]) = v;
        }
    }
    __syncthreads();

    for (int kt = 0; kt < nk; kt++) {
        float arg[CPT];
        float4 brg[F4];
        const bool has = (kt + 1 < nk);
        if (has) {
            int kb = (kt + 1) * BK;
#pragma unroll
            for (int j = 0; j < CPT; j++) {
                int gk = kb + ak0 + j;
                arg[j] = (gm < C_out && gk < K) ? Ap[(size_t)gm * lda + gk] : 0.f;
            }
#pragma unroll
            for (int i = 0; i < F4; i++) {
                int e = t + i * NT;
                if (e < TOT4) {
                    int k = kb + (e >> 5), c4 = (e & 31) * 4;
                    brg[i] = (k < K)
                                 ? *reinterpret_cast<const float4*>(Bp + (size_t)k * ldB + c4)
                                 : make_float4(0.f, 0.f, 0.f, 0.f);
                }
            }
        }
#pragma unroll
        for (int k = 0; k < BK; k++) {
            float4 x0 = *reinterpret_cast<const float4*>(&As[k * ASR + tm0]);
            float4 x1 = *reinterpret_cast<const float4*>(&As[k * ASR + tm0 + 4]);
            float a[8] = {x0.x, x0.y, x0.z, x0.w, x1.x, x1.y, x1.z, x1.w};
            ulonglong2 bv0 = *reinterpret_cast<const ulonglong2*>(&Bs[k * BN + tn0]);
            ulonglong2 bv1 = *reinterpret_cast<const ulonglong2*>(&Bs[k * BN + tn0 + 4]);
            unsigned long long bb[4] = {bv0.x, bv0.y, bv1.x, bv1.y};
#pragma unroll
            for (int i = 0; i < 8; i++) {
                unsigned long long ap = pack2(a[i], a[i]);
#pragma unroll
                for (int j = 0; j < 4; j++) fma2(acc[i][j], ap, bb[j]);
            }
        }
        __syncthreads();
        if (has) {
#pragma unroll
            for (int j = 0; j < CPT; j++) As[(ak0 + j) * ASR + am] = arg[j];
#pragma unroll
            for (int i = 0; i < F4; i++) {
                int e = t + i * NT;
                if (e < TOT4) {
                    int k = e >> 5, c4 = (e & 31) * 4;
                    *reinterpret_cast<float4*>(&Bs[k * BN + c4]) = brg[i];
                }
            }
            __syncthreads();
        }
    }

    const bool accf = (flags & 1);
    const bool relu = (flags & 2);
#pragma unroll
    for (int i = 0; i < 8; i++) {
        int m = bm0 + tm0 + i;
        if (m >= C_out) break;
        float bs = bias[m];
        float* cp = Cp + (size_t)m * ldB + tn0;
        float2 p0 = unpack2(acc[i][0]), p1 = unpack2(acc[i][1]);
        float2 p2 = unpack2(acc[i][2]), p3 = unpack2(acc[i][3]);
        float4 v0 = make_float4(p0.x + bs, p0.y + bs, p1.x + bs, p1.y + bs);
        float4 v1 = make_float4(p2.x + bs, p2.y + bs, p3.x + bs, p3.y + bs);
        if (accf) {
            float4 q0 = *reinterpret_cast<const float4*>(cp);
            float4 q1 = *reinterpret_cast<const float4*>(cp + 4);
            v0.x += q0.x; v0.y += q0.y; v0.z += q0.z; v0.w += q0.w;
            v1.x += q1.x; v1.y += q1.y; v1.z += q1.z; v1.w += q1.w;
        }
        if (relu) {
            v0.x = fmaxf(v0.x, 0.f); v0.y = fmaxf(v0.y, 0.f);
            v0.z = fmaxf(v0.z, 0.f); v0.w = fmaxf(v0.w, 0.f);
            v1.x = fmaxf(v1.x, 0.f); v1.y = fmaxf(v1.y, 0.f);
            v1.z = fmaxf(v1.z, 0.f); v1.w = fmaxf(v1.w, 0.f);
        }
        *reinterpret_cast<float4*>(cp) = v0;
        *reinterpret_cast<float4*>(cp + 4) = v1;
    }
}

// ---------------- final transpose ----------------
__global__ __launch_bounds__(256) void ftrans_kernel(const float* __restrict__ t13,
                                                     float* __restrict__ out, int B) {
    __shared__ float sm[128 * 19];
    int b0 = blockIdx.x * 128;
    int m = blockIdx.y, ho = blockIdx.z;
    int t = threadIdx.x;
    for (int idx = t; idx < 18 * 128; idx += 256) {
        int l = idx >> 7, b = idx & 127;
        sm[b * 19 + l] = t13[((size_t)(ho * 512 + m) * 18 + l) * B + b0 + b];
    }
    __syncthreads();
    for (int idx = t; idx < 128 * 18; idx += 256) {
        int b = idx / 18, l = idx - 18 * b;
        out[((size_t)(b0 + b) * 512 + m) * 54 + ho * 18 + l] = sm[b * 19 + l];
    }
}

// ---------------- host launcher ----------------
extern "C" void kernel_launch(void* const* d_in, const int* in_sizes, int n_in,
                              void* d_out, int out_size) {
    const float* x   = (const float*)d_in[0];
    const float* W0a = (const float*)d_in[1];
    const float* b0a = (const float*)d_in[2];
    const float* Wl0 = (const float*)d_in[3];
    const float* bl0 = (const float*)d_in[4];
    const float* W0b = (const float*)d_in[5];
    const float* b0b = (const float*)d_in[6];
    const float* Wr0 = (const float*)d_in[7];
    const float* br0 = (const float*)d_in[8];
    const float* W0c = (const float*)d_in[9];
    const float* b0c = (const float*)d_in[10];
    const float* W1  = (const float*)d_in[11];
    const float* b1  = (const float*)d_in[12];
    const float* Wl1 = (const float*)d_in[13];
    const float* bl1 = (const float*)d_in[14];
    const float* W2  = (const float*)d_in[15];
    const float* b2  = (const float*)d_in[16];
    const float* Wra = (const float*)d_in[17];
    const float* bra = (const float*)d_in[18];
    const float* Wa  = (const float*)d_in[19];
    const float* ba  = (const float*)d_in[20];
    const float* W3  = (const float*)d_in[21];
    const float* b3  = (const float*)d_in[22];
    const float* Wl2 = (const float*)d_in[23];
    const float* bl2 = (const float*)d_in[24];
    const float* W4  = (const float*)d_in[25];
    const float* b4  = (const float*)d_in[26];
    const float* Wrb = (const float*)d_in[27];
    const float* brb = (const float*)d_in[28];
    const float* Wb  = (const float*)d_in[29];
    const float* bb  = (const float*)d_in[30];

    const int B = in_sizes[0] / (5 * 127);
    const int nb = B / 128;
    const int N81 = 81 * B, N41 = 41 * B, N18 = 18 * B;

    float *xT, *t0, *t1, *t2, *t3, *t5, *t6, *t7, *t8, *t9, *t10, *t12, *t13;
    float *wp0b, *wp1, *wp2, *wp3, *wp4, *wpb;
    cudaGetSymbolAddress((void**)&xT, g_xT);
    cudaGetSymbolAddress((void**)&t0, g_t0);
    cudaGetSymbolAddress((void**)&t1, g_t1);
    cudaGetSymbolAddress((void**)&t2, g_t2);
    cudaGetSymbolAddress((void**)&t3, g_t3);
    cudaGetSymbolAddress((void**)&t5, g_t5);
    cudaGetSymbolAddress((void**)&t6, g_t6);
    cudaGetSymbolAddress((void**)&t7, g_t7);
    cudaGetSymbolAddress((void**)&t8, g_t8);
    cudaGetSymbolAddress((void**)&t9, g_t9);
    cudaGetSymbolAddress((void**)&t10, g_t10);
    cudaGetSymbolAddress((void**)&t12, g_t12);
    cudaGetSymbolAddress((void**)&t13, g_t13);
    cudaGetSymbolAddress((void**)&wp0b, g_wp0b);
    cudaGetSymbolAddress((void**)&wp1, g_wp1);
    cudaGetSymbolAddress((void**)&wp2, g_wp2);
    cudaGetSymbolAddress((void**)&wp3, g_wp3);
    cudaGetSymbolAddress((void**)&wp4, g_wp4);
    cudaGetSymbolAddress((void**)&wpb, g_wpb);

    P6 p; p.s0 = W0b; p.s1 = W1; p.s2 = W2; p.s3 = W3; p.s4 = W4; p.s5 = Wb;
    p.d0 = wp0b; p.d1 = wp1; p.d2 = wp2; p.d3 = wp3; p.d4 = wp4; p.d5 = wpb;
    permute_all_kernel<<<(667350 + 255) / 256, 256>>>(p);

    xpose_kernel<<<dim3(4, B / 32, 5), dim3(32, 8)>>>(x, xT, B);

    // ---- block 0 ----
    conv0a_kernel<<<(127 * B + 255) / 256, 256>>>(xT, W0a, b0a, t0, B);
    gemm_kernel<48, true><<<dim3(25 * nb, 2, 1), 96>>>(Wl0, 127, bl0, t0, t1,
                                                       127, 81, 0, 0, 0, B, 2);
    gemm_kernel<32, false><<<dim3(N81 / 128, 1, 5), 64>>>(wp0b, 15, b0b, t1, t2,
                                                          5, 25, 3, 1, 5, N81, 0);
    gemm_kernel<48, true><<<dim3(5 * nb, 2, 1), 96>>>(Wr0, 127, br0, xT, t3,
                                                      127, 81, 0, 0, 0, B, 0);
    gemm_kernel<32, false><<<dim3(N81 / 128, 1, 5), 64>>>(W0c, 1, b0c, t3, t2,
                                                          1, 25, 1, 0, 5, N81, 1);
    // t2 = x1

    // ---- block 1 ----
    gemm_kernel<48, false><<<dim3(N81 / 128, 2, 5), 96>>>(wp1, 75, b1, t2, t5,
                                                          25, 75, 3, 1, 5, N81, 0);
    gemm_kernel<48, true><<<dim3(375 * nb, 1, 1), 96>>>(Wl1, 81, bl1, t5, t6,
                                                        81, 41, 0, 0, 0, B, 2);
    gemm_kernel<32, false><<<dim3(N41 / 128, 5, 5), 64>>>(wp2, 225, b2, t6, t7,
                                                          75, 150, 3, 1, 5, N41, 0);
    gemm_kernel<48, true><<<dim3(125 * nb, 1, 1), 96>>>(Wra, 81, bra, t2, t8,
                                                        81, 41, 0, 0, 0, B, 0);
    gemm_kernel<32, false><<<dim3(N41 / 128, 5, 5), 64>>>(Wa, 25, ba, t8, t7,
                                                          25, 150, 1, 0, 5, N41, 1);
    // t7 = x2

    // ---- block 2 ----
    gemm_kernel<64, false><<<dim3(N41 / 128, 5, 4), 128>>>(wp3, 300, b3, t7, t9,
                                                           150, 300, 2, 0, 5, N41, 0);
    gemm_kernel<32, true><<<dim3(1200 * nb, 1, 1), 64>>>(Wl2, 41, bl2, t9, t10,
                                                         41, 18, 0, 0, 0, B, 2);
    gemm_kernel<128, false, 32><<<dim3(N18 / 128, 4, 3), 256>>>(wp4, 600, b4, t10, t13,
                                                                300, 512, 2, 0, 4, N18, 0);
    gemm_kernel<32, true><<<dim3(750 * nb, 1, 1), 64>>>(Wrb, 41, brb, t7, t12,
                                                        41, 18, 0, 0, 0, B, 0);
    gemm_kernel<128, false, 32><<<dim3(N18 / 128, 4, 3), 256>>>(wpb, 450, bb, t12, t13,
                                                                150, 512, 3, 0, 5, N18, 1);
    ftrans_kernel<<<dim3(B / 128, 512, 3), 256>>>(t13, (float*)d_out, B);
}

// round 17
// speedup vs baseline: 2.5162x; 1.5977x over previous
#include <cuda_runtime.h>

// ----------------------------------------------------------------------------
// complex_feature_renet — GB300 sm_103a, round 16
// EXACT revert to the round-3 design that benched 3249us (best known).
// [H][C][L][B] layout. Convs: per-h GEMM (M=C_out, K=khv*C_in, N=L*B).
// Linears: grouped GEMM (M=O, K, N=B per group). FFMA2 (fma.rn.f32x2)
// register-tiled mainloop, TM=8 x TN=8, BN=128, BK=16, single-buffer smem.
// ----------------------------------------------------------------------------

#define BFIX 1024

__device__ float g_xT [5 * 127 * BFIX];
__device__ float g_t0 [5 * 5   * 127 * BFIX];
__device__ float g_t1 [5 * 5   * 81  * BFIX];
__device__ float g_t2 [5 * 25  * 81  * BFIX];
__device__ float g_t3 [5 * 1   * 81  * BFIX];
__device__ float g_t5 [5 * 75  * 81  * BFIX];
__device__ float g_t6 [5 * 75  * 41  * BFIX];
__device__ float g_t7 [5 * 150 * 41  * BFIX];
__device__ float g_t8 [5 * 25  * 41  * BFIX];
__device__ float g_t9 [4 * 300 * 41  * BFIX];
__device__ float g_t10[4 * 300 * 18  * BFIX];
__device__ float g_t12[5 * 150 * 18  * BFIX];
__device__ float g_t13[3 * 512 * 18  * BFIX];

__device__ float g_wp0b[25  * 15 ];
__device__ float g_wp1 [75  * 75 ];
__device__ float g_wp2 [150 * 225];
__device__ float g_wp3 [300 * 300];
__device__ float g_wp4 [512 * 600];
__device__ float g_wpb [512 * 450];

// ---------------- f32x2 helpers ----------------
__device__ __forceinline__ unsigned long long pack2(float x, float y) {
    unsigned long long r;
    asm("mov.b64 %0, {%1, %2};" : "=l"(r) : "f"(x), "f"(y));
    return r;
}
__device__ __forceinline__ void fma2(unsigned long long& c, unsigned long long a,
                                     unsigned long long b) {
    asm("fma.rn.f32x2 %0, %1, %2, %0;" : "+l"(c) : "l"(a), "l"(b));
}
__device__ __forceinline__ float2 unpack2(unsigned long long v) {
    float2 r;
    asm("mov.b64 {%0, %1}, %2;" : "=f"(r.x), "=f"(r.y) : "l"(v));
    return r;
}

// ---------------- fused weight fold ----------------
struct P6 {
    const float *s0, *s1, *s2, *s3, *s4, *s5;
    float *d0, *d1, *d2, *d3, *d4, *d5;
};
__global__ void permute_all_kernel(P6 p) {
    int idx = blockIdx.x * blockDim.x + threadIdx.x;
    const float* s; float* d; int C, KH, base;
    if (idx < 375)        { s = p.s0; d = p.d0; C = 5;   KH = 3; base = 0; }
    else if (idx < 6000)  { s = p.s1; d = p.d1; C = 25;  KH = 3; base = 375; }
    else if (idx < 39750) { s = p.s2; d = p.d2; C = 75;  KH = 3; base = 6000; }
    else if (idx < 129750){ s = p.s3; d = p.d3; C = 150; KH = 2; base = 39750; }
    else if (idx < 436950){ s = p.s4; d = p.d4; C = 300; KH = 2; base = 129750; }
    else if (idx < 667350){ s = p.s5; d = p.d5; C = 150; KH = 3; base = 436950; }
    else return;
    int local = idx - base;
    int o = local / (KH * C);
    int rem = local - o * (KH * C);
    int dh = rem / C;
    int i = rem - dh * C;
    d[local] = s[(o * C + i) * KH + dh];
}

// ---------------- x transpose ----------------
__global__ void xpose_kernel(const float* __restrict__ x, float* __restrict__ xT,
                             int B) {
    __shared__ float sm[32][33];
    int h = blockIdx.z;
    int l0 = blockIdx.x * 32, b0 = blockIdx.y * 32;
    int tx = threadIdx.x, ty = threadIdx.y;
#pragma unroll
    for (int j = 0; j < 4; j++) {
        int b = b0 + ty + j * 8, l = l0 + tx;
        if (l < 127) sm[ty + j * 8][tx] = x[((size_t)b * 5 + h) * 127 + l];
    }
    __syncthreads();
#pragma unroll
    for (int j = 0; j < 4; j++) {
        int l = l0 + ty + j * 8, b = b0 + tx;
        if (l < 127) xT[((size_t)h * 127 + l) * B + b] = sm[tx][ty + j * 8];
    }
}

// ---------------- conv0a ----------------
__global__ void conv0a_kernel(const float* __restrict__ xT, const float* __restrict__ w,
                              const float* __restrict__ bias, float* __restrict__ out,
                              int B) {
    int n = blockIdx.x * blockDim.x + threadIdx.x;
    int N = 127 * B;
    if (n >= N) return;
    float xv[5];
#pragma unroll
    for (int h = 0; h < 5; h++) xv[h] = xT[(size_t)h * N + n];
    float wv[5][3];
#pragma unroll
    for (int c = 0; c < 5; c++)
#pragma unroll
        for (int dh = 0; dh < 3; dh++) wv[c][dh] = w[c * 3 + dh];
#pragma unroll
    for (int ho = 0; ho < 5; ho++) {
#pragma unroll
        for (int c = 0; c < 5; c++) {
            float acc = bias[c];
#pragma unroll
            for (int dh = 0; dh < 3; dh++) {
                int hi = ho + dh - 1;
                if (hi >= 0 && hi < 5) acc = fmaf(wv[c][dh], xv[hi], acc);
            }
            out[(size_t)(ho * 5 + c) * N + n] = acc;
        }
    }
}

// ---------------- unified GEMM (round-3 proven design) ----------------
// flags: bit0 = accumulate, bit1 = relu
template <int BM, bool LINM>
__global__ __launch_bounds__(BM * 2, (BM == 128 ? 2 : BM == 64 ? 4 : BM == 48 ? 4 : 6))
void gemm_kernel(const float* __restrict__ A, int lda,
                 const float* __restrict__ bias,
                 const float* __restrict__ Bb, float* __restrict__ Cb,
                 int C_in, int C_out, int KH, int pad, int H_in,
                 int ldB, int flags) {
    constexpr int NT = BM * 2, BN = 128, BK = 16, ASR = BM + 4;
    constexpr int F4 = (512 + NT - 1) / NT;  // float4 loads per thread for B tile
    __shared__ __align__(16) float As[BK * ASR];
    __shared__ __align__(16) float Bs[BK * BN];

    const int t = threadIdx.x;
    const int bm0 = blockIdx.y * BM;

    int K;
    const float* Ap;
    const float* Bp;
    float* Cp;
    if (LINM) {
        K = C_in;
        int nb = ldB >> 7;
        int g = blockIdx.x / nb;
        int nbi = blockIdx.x - g * nb;
        Ap = A;
        Bp = Bb + (size_t)g * K * ldB + nbi * BN;
        Cp = Cb + (size_t)g * C_out * ldB + nbi * BN;
    } else {
        int ho = blockIdx.z;
        int hs = ho - pad;
        int h0 = hs > 0 ? hs : 0;
        int he = hs + KH; if (he > H_in) he = H_in;
        K = (he - h0) * C_in;
        Ap = A + (h0 - hs) * C_in;
        Bp = Bb + (size_t)h0 * C_in * ldB + (size_t)blockIdx.x * BN;
        Cp = Cb + (size_t)ho * C_out * ldB + (size_t)blockIdx.x * BN;
    }

    const int am = t >> 1;
    const int ak0 = (t & 1) * 8;
    const int gm = bm0 + am;
    const int tidm = t / 16, tidn = t % 16;
    const int tm0 = tidm * 8, tn0 = tidn * 8;

    unsigned long long acc[8][4];
#pragma unroll
    for (int i = 0; i < 8; i++)
#pragma unroll
        for (int j = 0; j < 4; j++) acc[i][j] = 0ull;

    const int nk = (K + BK - 1) / BK;

    // tile 0 -> smem
#pragma unroll
    for (int j = 0; j < 8; j++) {
        int gk = ak0 + j;
        float v = (gm < C_out && gk < K) ? Ap[(size_t)gm * lda + gk] : 0.f;
        As[gk * ASR + am] = v;
    }
#pragma unroll
    for (int i = 0; i < F4; i++) {
        int e = t + i * NT;
        if (e < 512) {
            int k = e >> 5, c4 = (e & 31) * 4;
            float4 v = make_float4(0.f, 0.f, 0.f, 0.f);
            if (k < K) v = *reinterpret_cast<const float4*>(Bp + (size_t)k * ldB + c4);
            *reinterpret_cast<float4*>(&Bs[k * BN + c4]) = v;
        }
    }
    __syncthreads();

    for (int kt = 0; kt < nk; kt++) {
        float arg[8];
        float4 brg[F4];
        const bool has = (kt + 1 < nk);
        if (has) {
            int kb = (kt + 1) * BK;
#pragma unroll
            for (int j = 0; j < 8; j++) {
                int gk = kb + ak0 + j;
                arg[j] = (gm < C_out && gk < K) ? Ap[(size_t)gm * lda + gk] : 0.f;
            }
#pragma unroll
            for (int i = 0; i < F4; i++) {
                int e = t + i * NT;
                if (e < 512) {
                    int k = kb + (e >> 5), c4 = (e & 31) * 4;
                    brg[i] = (k < K)
                                 ? *reinterpret_cast<const float4*>(Bp + (size_t)k * ldB + c4)
                                 : make_float4(0.f, 0.f, 0.f, 0.f);
                }
            }
        }
#pragma unroll
        for (int k = 0; k < BK; k++) {
            float4 x0 = *reinterpret_cast<const float4*>(&As[k * ASR + tm0]);
            float4 x1 = *reinterpret_cast<const float4*>(&As[k * ASR + tm0 + 4]);
            float a[8] = {x0.x, x0.y, x0.z, x0.w, x1.x, x1.y, x1.z, x1.w};
            ulonglong2 bv0 = *reinterpret_cast<const ulonglong2*>(&Bs[k * BN + tn0]);
            ulonglong2 bv1 = *reinterpret_cast<const ulonglong2*>(&Bs[k * BN + tn0 + 4]);
            unsigned long long bb[4] = {bv0.x, bv0.y, bv1.x, bv1.y};
#pragma unroll
            for (int i = 0; i < 8; i++) {
                unsigned long long ap = pack2(a[i], a[i]);
#pragma unroll
                for (int j = 0; j < 4; j++) fma2(acc[i][j], ap, bb[j]);
            }
        }
        __syncthreads();
        if (has) {
#pragma unroll
            for (int j = 0; j < 8; j++) As[(ak0 + j) * ASR + am] = arg[j];
#pragma unroll
            for (int i = 0; i < F4; i++) {
                int e = t + i * NT;
                if (e < 512) {
                    int k = e >> 5, c4 = (e & 31) * 4;
                    *reinterpret_cast<float4*>(&Bs[k * BN + c4]) = brg[i];
                }
            }
            __syncthreads();
        }
    }

    const bool accf = (flags & 1);
    const bool relu = (flags & 2);
#pragma unroll
    for (int i = 0; i < 8; i++) {
        int m = bm0 + tm0 + i;
        if (m >= C_out) break;
        float bs = bias[m];
        float* cp = Cp + (size_t)m * ldB + tn0;
        float2 p0 = unpack2(acc[i][0]), p1 = unpack2(acc[i][1]);
        float2 p2 = unpack2(acc[i][2]), p3 = unpack2(acc[i][3]);
        float4 v0 = make_float4(p0.x + bs, p0.y + bs, p1.x + bs, p1.y + bs);
        float4 v1 = make_float4(p2.x + bs, p2.y + bs, p3.x + bs, p3.y + bs);
        if (accf) {
            float4 q0 = *reinterpret_cast<const float4*>(cp);
            float4 q1 = *reinterpret_cast<const float4*>(cp + 4);
            v0.x += q0.x; v0.y += q0.y; v0.z += q0.z; v0.w += q0.w;
            v1.x += q1.x; v1.y += q1.y; v1.z += q1.z; v1.w += q1.w;
        }
        if (relu) {
            v0.x = fmaxf(v0.x, 0.f); v0.y = fmaxf(v0.y, 0.f);
            v0.z = fmaxf(v0.z, 0.f); v0.w = fmaxf(v0.w, 0.f);
            v1.x = fmaxf(v1.x, 0.f); v1.y = fmaxf(v1.y, 0.f);
            v1.z = fmaxf(v1.z, 0.f); v1.w = fmaxf(v1.w, 0.f);
        }
        *reinterpret_cast<float4*>(cp) = v0;
        *reinterpret_cast<float4*>(cp + 4) = v1;
    }
}

// ---------------- final transpose ----------------
__global__ __launch_bounds__(256) void ftrans_kernel(const float* __restrict__ t13,
                                                     float* __restrict__ out, int B) {
    __shared__ float sm[128 * 19];
    int b0 = blockIdx.x * 128;
    int m = blockIdx.y, ho = blockIdx.z;
    int t = threadIdx.x;
    for (int idx = t; idx < 18 * 128; idx += 256) {
        int l = idx >> 7, b = idx & 127;
        sm[b * 19 + l] = t13[((size_t)(ho * 512 + m) * 18 + l) * B + b0 + b];
    }
    __syncthreads();
    for (int idx = t; idx < 128 * 18; idx += 256) {
        int b = idx / 18, l = idx - 18 * b;
        out[((size_t)(b0 + b) * 512 + m) * 54 + ho * 18 + l] = sm[b * 19 + l];
    }
}

// ---------------- host launcher ----------------
extern "C" void kernel_launch(void* const* d_in, const int* in_sizes, int n_in,
                              void* d_out, int out_size) {
    const float* x   = (const float*)d_in[0];
    const float* W0a = (const float*)d_in[1];
    const float* b0a = (const float*)d_in[2];
    const float* Wl0 = (const float*)d_in[3];
    const float* bl0 = (const float*)d_in[4];
    const float* W0b = (const float*)d_in[5];
    const float* b0b = (const float*)d_in[6];
    const float* Wr0 = (const float*)d_in[7];
    const float* br0 = (const float*)d_in[8];
    const float* W0c = (const float*)d_in[9];
    const float* b0c = (const float*)d_in[10];
    const float* W1  = (const float*)d_in[11];
    const float* b1  = (const float*)d_in[12];
    const float* Wl1 = (const float*)d_in[13];
    const float* bl1 = (const float*)d_in[14];
    const float* W2  = (const float*)d_in[15];
    const float* b2  = (const float*)d_in[16];
    const float* Wra = (const float*)d_in[17];
    const float* bra = (const float*)d_in[18];
    const float* Wa  = (const float*)d_in[19];
    const float* ba  = (const float*)d_in[20];
    const float* W3  = (const float*)d_in[21];
    const float* b3  = (const float*)d_in[22];
    const float* Wl2 = (const float*)d_in[23];
    const float* bl2 = (const float*)d_in[24];
    const float* W4  = (const float*)d_in[25];
    const float* b4  = (const float*)d_in[26];
    const float* Wrb = (const float*)d_in[27];
    const float* brb = (const float*)d_in[28];
    const float* Wb  = (const float*)d_in[29];
    const float* bb  = (const float*)d_in[30];

    const int B = in_sizes[0] / (5 * 127);
    const int nb = B / 128;
    const int N81 = 81 * B, N41 = 41 * B, N18 = 18 * B;

    float *xT, *t0, *t1, *t2, *t3, *t5, *t6, *t7, *t8, *t9, *t10, *t12, *t13;
    float *wp0b, *wp1, *wp2, *wp3, *wp4, *wpb;
    cudaGetSymbolAddress((void**)&xT, g_xT);
    cudaGetSymbolAddress((void**)&t0, g_t0);
    cudaGetSymbolAddress((void**)&t1, g_t1);
    cudaGetSymbolAddress((void**)&t2, g_t2);
    cudaGetSymbolAddress((void**)&t3, g_t3);
    cudaGetSymbolAddress((void**)&t5, g_t5);
    cudaGetSymbolAddress((void**)&t6, g_t6);
    cudaGetSymbolAddress((void**)&t7, g_t7);
    cudaGetSymbolAddress((void**)&t8, g_t8);
    cudaGetSymbolAddress((void**)&t9, g_t9);
    cudaGetSymbolAddress((void**)&t10, g_t10);
    cudaGetSymbolAddress((void**)&t12, g_t12);
    cudaGetSymbolAddress((void**)&t13, g_t13);
    cudaGetSymbolAddress((void**)&wp0b, g_wp0b);
    cudaGetSymbolAddress((void**)&wp1, g_wp1);
    cudaGetSymbolAddress((void**)&wp2, g_wp2);
    cudaGetSymbolAddress((void**)&wp3, g_wp3);
    cudaGetSymbolAddress((void**)&wp4, g_wp4);
    cudaGetSymbolAddress((void**)&wpb, g_wpb);

    P6 p; p.s0 = W0b; p.s1 = W1; p.s2 = W2; p.s3 = W3; p.s4 = W4; p.s5 = Wb;
    p.d0 = wp0b; p.d1 = wp1; p.d2 = wp2; p.d3 = wp3; p.d4 = wp4; p.d5 = wpb;
    permute_all_kernel<<<(667350 + 255) / 256, 256>>>(p);

    xpose_kernel<<<dim3(4, B / 32, 5), dim3(32, 8)>>>(x, xT, B);

    // ---- block 0 ----
    conv0a_kernel<<<(127 * B + 255) / 256, 256>>>(xT, W0a, b0a, t0, B);
    gemm_kernel<48, true><<<dim3(25 * nb, 2, 1), 96>>>(Wl0, 127, bl0, t0, t1,
                                                       127, 81, 0, 0, 0, B, 2);
    gemm_kernel<32, false><<<dim3(N81 / 128, 1, 5), 64>>>(wp0b, 15, b0b, t1, t2,
                                                          5, 25, 3, 1, 5, N81, 0);
    gemm_kernel<48, true><<<dim3(5 * nb, 2, 1), 96>>>(Wr0, 127, br0, xT, t3,
                                                      127, 81, 0, 0, 0, B, 0);
    gemm_kernel<32, false><<<dim3(N81 / 128, 1, 5), 64>>>(W0c, 1, b0c, t3, t2,
                                                          1, 25, 1, 0, 5, N81, 1);
    // t2 = x1

    // ---- block 1 ----
    gemm_kernel<48, false><<<dim3(N81 / 128, 2, 5), 96>>>(wp1, 75, b1, t2, t5,
                                                          25, 75, 3, 1, 5, N81, 0);
    gemm_kernel<48, true><<<dim3(375 * nb, 1, 1), 96>>>(Wl1, 81, bl1, t5, t6,
                                                        81, 41, 0, 0, 0, B, 2);
    gemm_kernel<32, false><<<dim3(N41 / 128, 5, 5), 64>>>(wp2, 225, b2, t6, t7,
                                                          75, 150, 3, 1, 5, N41, 0);
    gemm_kernel<48, true><<<dim3(125 * nb, 1, 1), 96>>>(Wra, 81, bra, t2, t8,
                                                        81, 41, 0, 0, 0, B, 0);
    gemm_kernel<32, false><<<dim3(N41 / 128, 5, 5), 64>>>(Wa, 25, ba, t8, t7,
                                                          25, 150, 1, 0, 5, N41, 1);
    // t7 = x2

    // ---- block 2 ----
    gemm_kernel<64, false><<<dim3(N41 / 128, 5, 4), 128>>>(wp3, 300, b3, t7, t9,
                                                           150, 300, 2, 0, 5, N41, 0);
    gemm_kernel<32, true><<<dim3(1200 * nb, 1, 1), 64>>>(Wl2, 41, bl2, t9, t10,
                                                         41, 18, 0, 0, 0, B, 2);
    gemm_kernel<128, false><<<dim3(N18 / 128, 4, 3), 256>>>(wp4, 600, b4, t10, t13,
                                                            300, 512, 2, 0, 4, N18, 0);
    gemm_kernel<32, true><<<dim3(750 * nb, 1, 1), 64>>>(Wrb, 41, brb, t7, t12,
                                                        41, 18, 0, 0, 0, B, 0);
    gemm_kernel<128, false><<<dim3(N18 / 128, 4, 3), 256>>>(wpb, 450, bb, t12, t13,
                                                            150, 512, 3, 0, 5, N18, 1);
    ftrans_kernel<<<dim3(B / 128, 512, 3), 256>>>(t13, (float*)d_out, B);
}